// round 16
// baseline (speedup 1.0000x reference)
#include <cuda_runtime.h>
#include <math.h>

// ============================================================================
// Final kernel. The whole problem reduces algebraically to:
//   S[b,ci]   = sum over 256x256 spatial plane of x        (100.66 MB read)
//   mean[b,co]= (sum_ci S[b,ci] * sum_pq W[ci,co,p,q]) / 258^2
//   out[b]    = 10 * logsumexp_co(mean[b,co] + bias[co])
// The plane-sum reduction is the entire cost and runs at ~98% of the 8 TB/s
// HBM spec end-to-end (12.77us vs 12.58us zero-overhead floor). Measured
// plateau across 5 structural variants => this is the platform roofline.
//
// Structure: k_reduce (768 CTAs = exactly one wave, plain float4 loads,
// plain partial stores, no atomics/fences) + k_final launched as a PDL
// secondary so its prologue (weight/bias prep) overlaps k_reduce's tail.
// ============================================================================

#define B_   128
#define CIN  3
#define COUT 16
#define HW   (256 * 256)          // 65536 elements per plane
#define PLANE_F4 (HW / 4)         // 16384 float4 per plane
#define NPLANES (B_ * CIN)        // 384
#define BLOCKS_PER_PLANE 2
#define THREADS 256
#define NBLOCKS (NPLANES * BLOCKS_PER_PLANE)                   // 768 -> single wave
#define F4_PER_THREAD (PLANE_F4 / BLOCKS_PER_PLANE / THREADS)  // 32

// Per-(plane,chunk) partial sums — plain stores, no zeroing, no atomics.
__device__ float g_partial[NBLOCKS];

__global__ __launch_bounds__(THREADS) void k_reduce(const float4* __restrict__ x) {
    const int plane = blockIdx.x >> 1;
    const int chunk = blockIdx.x & 1;
    const float4* base = x + (size_t)plane * PLANE_F4
                           + (size_t)chunk * (PLANE_F4 / BLOCKS_PER_PLANE);

    float s = 0.0f;
    #pragma unroll 16
    for (int i = 0; i < F4_PER_THREAD; i++) {
        float4 v = base[threadIdx.x + i * THREADS];
        s += (v.x + v.y) + (v.z + v.w);
    }

    // warp reduce
    #pragma unroll
    for (int o = 16; o > 0; o >>= 1)
        s += __shfl_xor_sync(0xFFFFFFFFu, s, o);

    __shared__ float ws[THREADS / 32];
    if ((threadIdx.x & 31) == 0) ws[threadIdx.x >> 5] = s;
    __syncthreads();

    if (threadIdx.x == 0) {
        float t = 0.0f;
        #pragma unroll
        for (int w = 0; w < THREADS / 32; w++) t += ws[w];
        g_partial[blockIdx.x] = t;
    }
    __syncthreads();
    // PDL: make writes visible to the dependent grid and let it proceed.
    cudaTriggerProgrammaticLaunchCompletion();
}

// Epilogue (PDL secondary): prologue overlaps k_reduce's tail.
__global__ __launch_bounds__(128) void k_final(
    const float* __restrict__ weight,
    const float* __restrict__ bias,
    float*       __restrict__ out)
{
    const int t = threadIdx.x;

    // --- independent work (overlaps primary): kernel-weight sums + bias ---
    __shared__ float wsum[CIN][COUT];
    if (t < CIN * COUT) {
        int ci = t / COUT, co = t % COUT;
        float acc = 0.0f;
        #pragma unroll
        for (int pq = 0; pq < 9; pq++)
            acc += weight[(ci * COUT + co) * 9 + pq];
        wsum[ci][co] = acc;
    }
    __syncthreads();

    float w0[COUT], w1[COUT], w2[COUT], bch[COUT];
    #pragma unroll
    for (int co = 0; co < COUT; co++) {
        w0[co] = wsum[0][co];
        w1[co] = wsum[1][co];
        w2[co] = wsum[2][co];
        bch[co] = bias[co];
    }

    // --- wait for k_reduce's partials ---
    cudaGridDependencySynchronize();

    // thread t = batch index: 6 partials at g_partial[t*6]; pair-starts are
    // even indices -> 8B-aligned float2 loads.
    const float2 pa = *reinterpret_cast<const float2*>(&g_partial[t * 6 + 0]);
    const float2 pb = *reinterpret_cast<const float2*>(&g_partial[t * 6 + 2]);
    const float2 pc = *reinterpret_cast<const float2*>(&g_partial[t * 6 + 4]);
    const float s0 = pa.x + pa.y;
    const float s1 = pb.x + pb.y;
    const float s2 = pc.x + pc.y;
    const float inv = 1.0f / (258.0f * 258.0f);

    float y[COUT];
    float m = -INFINITY;
    #pragma unroll
    for (int co = 0; co < COUT; co++) {
        float v = (s0 * w0[co] + s1 * w1[co] + s2 * w2[co]) * inv + bch[co];
        y[co] = v;
        m = fmaxf(m, v);
    }
    float e = 0.0f;
    #pragma unroll
    for (int co = 0; co < COUT; co++)
        e += expf(y[co] - m);

    out[t] = 10.0f * (m + logf(e));
}

extern "C" void kernel_launch(void* const* d_in, const int* in_sizes, int n_in,
                              void* d_out, int out_size) {
    const float4* x      = (const float4*)d_in[0];
    const float*  weight = (const float*)d_in[1];
    const float*  bias   = (const float*)d_in[2];
    float* out = (float*)d_out;

    k_reduce<<<NBLOCKS, THREADS>>>(x);

    cudaLaunchConfig_t cfg = {};
    cfg.gridDim  = dim3(1, 1, 1);
    cfg.blockDim = dim3(128, 1, 1);
    cfg.dynamicSmemBytes = 0;
    cfg.stream = 0;
    cudaLaunchAttribute attrs[1];
    attrs[0].id = cudaLaunchAttributeProgrammaticStreamSerialization;
    attrs[0].val.programmaticStreamSerializationAllowed = 1;
    cfg.attrs = attrs;
    cfg.numAttrs = 1;
    cudaLaunchKernelEx(&cfg, k_final, weight, bias, out);
}

// round 17
// speedup vs baseline: 1.0025x; 1.0025x over previous
#include <cuda_runtime.h>
#include <math.h>

// ============================================================================
// FINAL. The problem reduces algebraically to:
//   S[b,ci]    = sum over the 256x256 spatial plane of x    (100.66 MB read)
//   mean[b,co] = (sum_ci S[b,ci] * sum_pq W[ci,co,p,q]) / 258^2
//   out[b]     = 10 * logsumexp_co(mean[b,co] + bias[co])
//
// The plane-sum reduction is the entire cost: 100.66 MB / 12.77us = 7.88 TB/s
// end-to-end = 98.5% of the 8 TB/s HBM spec (zero-overhead floor: 12.58us).
// Six structural variants plateau at this number -> platform roofline.
//
// Structure: k_reduce (768 CTAs = exactly one wave on 148/152 SMs, float4
// loads with unroll-16 MLP, plain partial stores — no zeroing/atomics/fences)
// + k_final launched as a PDL secondary so its prologue (weight/bias prep)
// overlaps k_reduce's tail; it grid-dep-syncs only before reading partials.
// ============================================================================

#define B_   128
#define CIN  3
#define COUT 16
#define HW   (256 * 256)          // 65536 elements per plane
#define PLANE_F4 (HW / 4)         // 16384 float4 per plane
#define NPLANES (B_ * CIN)        // 384
#define BLOCKS_PER_PLANE 2
#define THREADS 256
#define NBLOCKS (NPLANES * BLOCKS_PER_PLANE)                   // 768 -> single wave
#define F4_PER_THREAD (PLANE_F4 / BLOCKS_PER_PLANE / THREADS)  // 32

// Per-(plane,chunk) partial sums — plain stores, no zeroing, no atomics.
__device__ float g_partial[NBLOCKS];

__global__ __launch_bounds__(THREADS) void k_reduce(const float4* __restrict__ x) {
    const int plane = blockIdx.x >> 1;
    const int chunk = blockIdx.x & 1;
    const float4* base = x + (size_t)plane * PLANE_F4
                           + (size_t)chunk * (PLANE_F4 / BLOCKS_PER_PLANE);

    float s = 0.0f;
    #pragma unroll 16
    for (int i = 0; i < F4_PER_THREAD; i++) {
        float4 v = base[threadIdx.x + i * THREADS];
        s += (v.x + v.y) + (v.z + v.w);
    }

    // warp reduce
    #pragma unroll
    for (int o = 16; o > 0; o >>= 1)
        s += __shfl_xor_sync(0xFFFFFFFFu, s, o);

    __shared__ float ws[THREADS / 32];
    if ((threadIdx.x & 31) == 0) ws[threadIdx.x >> 5] = s;
    __syncthreads();

    if (threadIdx.x == 0) {
        float t = 0.0f;
        #pragma unroll
        for (int w = 0; w < THREADS / 32; w++) t += ws[w];
        g_partial[blockIdx.x] = t;
    }
    __syncthreads();
    // PDL: make writes visible to the dependent grid and let it proceed.
    cudaTriggerProgrammaticLaunchCompletion();
}

// Epilogue (PDL secondary): prologue overlaps k_reduce's tail.
__global__ __launch_bounds__(128) void k_final(
    const float* __restrict__ weight,
    const float* __restrict__ bias,
    float*       __restrict__ out)
{
    const int t = threadIdx.x;

    // --- independent work (overlaps primary): kernel-weight sums + bias ---
    __shared__ float wsum[CIN][COUT];
    if (t < CIN * COUT) {
        int ci = t / COUT, co = t % COUT;
        float acc = 0.0f;
        #pragma unroll
        for (int pq = 0; pq < 9; pq++)
            acc += weight[(ci * COUT + co) * 9 + pq];
        wsum[ci][co] = acc;
    }
    __syncthreads();

    float w0[COUT], w1[COUT], w2[COUT], bch[COUT];
    #pragma unroll
    for (int co = 0; co < COUT; co++) {
        w0[co] = wsum[0][co];
        w1[co] = wsum[1][co];
        w2[co] = wsum[2][co];
        bch[co] = bias[co];
    }

    // --- wait for k_reduce's partials ---
    cudaGridDependencySynchronize();

    // thread t = batch index: 6 partials at g_partial[t*6]; pair-starts are
    // even indices -> 8B-aligned float2 loads.
    const float2 pa = *reinterpret_cast<const float2*>(&g_partial[t * 6 + 0]);
    const float2 pb = *reinterpret_cast<const float2*>(&g_partial[t * 6 + 2]);
    const float2 pc = *reinterpret_cast<const float2*>(&g_partial[t * 6 + 4]);
    const float s0 = pa.x + pa.y;
    const float s1 = pb.x + pb.y;
    const float s2 = pc.x + pc.y;
    const float inv = 1.0f / (258.0f * 258.0f);

    float y[COUT];
    float m = -INFINITY;
    #pragma unroll
    for (int co = 0; co < COUT; co++) {
        float v = (s0 * w0[co] + s1 * w1[co] + s2 * w2[co]) * inv + bch[co];
        y[co] = v;
        m = fmaxf(m, v);
    }
    float e = 0.0f;
    #pragma unroll
    for (int co = 0; co < COUT; co++)
        e += expf(y[co] - m);

    out[t] = 10.0f * (m + logf(e));
}

extern "C" void kernel_launch(void* const* d_in, const int* in_sizes, int n_in,
                              void* d_out, int out_size) {
    const float4* x      = (const float4*)d_in[0];
    const float*  weight = (const float*)d_in[1];
    const float*  bias   = (const float*)d_in[2];
    float* out = (float*)d_out;

    k_reduce<<<NBLOCKS, THREADS>>>(x);

    cudaLaunchConfig_t cfg = {};
    cfg.gridDim  = dim3(1, 1, 1);
    cfg.blockDim = dim3(128, 1, 1);
    cfg.dynamicSmemBytes = 0;
    cfg.stream = 0;
    cudaLaunchAttribute attrs[1];
    attrs[0].id = cudaLaunchAttributeProgrammaticStreamSerialization;
    attrs[0].val.programmaticStreamSerializationAllowed = 1;
    cfg.attrs = attrs;
    cfg.numAttrs = 1;
    cudaLaunchKernelEx(&cfg, k_final, weight, bias, out);
}